// round 11
// baseline (speedup 1.0000x reference)
#include <cuda_runtime.h>
#include <math.h>

#define BN 2
#define LL 2048
#define DD 1024
#define HH 16
#define HD 64
#define BH (BN*HH)

// Static scratch (runtime allocation is forbidden).
__device__ float g_Q[BN*LL*DD];
__device__ float g_K[BN*LL*DD];
__device__ float g_V[BN*LL*DD];
__device__ float g_G[BN*LL*DD];
__device__ float g_O[BN*LL*DD];

// ---------------------------------------------------------------------------
// Tiled SGEMM: C[M,N] = A[M,K] @ W[N,K]^T + bias[N], optional sigmoid.
// 128x128 tile, BK=16, 256 threads, 8x8 register blocking.
// Double-buffered smem + register prefetch: ONE __syncthreads per k-iter.
// Vectorized (float4) epilogue. M%128==0, N%128==0, K%32==0.
// ---------------------------------------------------------------------------
template<int ACT>
__global__ __launch_bounds__(256, 2)
void gemm_bias_kernel(const float* __restrict__ A,
                      const float* __restrict__ W,
                      const float* __restrict__ bias,
                      float* __restrict__ C,
                      int M, int N, int K) {
    __shared__ float As[2][16][132];
    __shared__ float Ws[2][16][132];
    const int tid = threadIdx.x;
    const int tx = tid & 15;          // col group (8 cols)
    const int ty = tid >> 4;          // row group (8 rows)
    const int row0 = blockIdx.y * 128;
    const int col0 = blockIdx.x * 128;
    const int lr = tid >> 1;          // 0..127
    const int lk = (tid & 1) * 8;     // 0 or 8

    const float* Arow = &A[(size_t)(row0 + lr) * K + lk];
    const float* Wrow = &W[(size_t)(col0 + lr) * K + lk];

    float acc[8][8] = {};

    const int NIT = K / 16;

    // load k-slab 0 and stage into buffer 0
    {
        float4 a0 = *(const float4*)&Arow[0];
        float4 a1 = *(const float4*)&Arow[4];
        float4 w0 = *(const float4*)&Wrow[0];
        float4 w1 = *(const float4*)&Wrow[4];
        As[0][lk+0][lr] = a0.x; As[0][lk+1][lr] = a0.y; As[0][lk+2][lr] = a0.z; As[0][lk+3][lr] = a0.w;
        As[0][lk+4][lr] = a1.x; As[0][lk+5][lr] = a1.y; As[0][lk+6][lr] = a1.z; As[0][lk+7][lr] = a1.w;
        Ws[0][lk+0][lr] = w0.x; Ws[0][lk+1][lr] = w0.y; Ws[0][lk+2][lr] = w0.z; Ws[0][lk+3][lr] = w0.w;
        Ws[0][lk+4][lr] = w1.x; Ws[0][lk+5][lr] = w1.y; Ws[0][lk+6][lr] = w1.z; Ws[0][lk+7][lr] = w1.w;
    }
    __syncthreads();

    for (int it = 0; it < NIT; it++) {
        const int buf = it & 1;
        const bool has_next = (it + 1 < NIT);

        // issue next slab's global loads first (latency overlapped by compute)
        float4 a0, a1, w0, w1;
        if (has_next) {
            int koff = (it + 1) * 16;
            a0 = *(const float4*)&Arow[koff];
            a1 = *(const float4*)&Arow[koff + 4];
            w0 = *(const float4*)&Wrow[koff];
            w1 = *(const float4*)&Wrow[koff + 4];
        }

        #pragma unroll
        for (int k = 0; k < 16; k++) {
            float a[8], b[8];
            #pragma unroll
            for (int i = 0; i < 8; i++) a[i] = As[buf][k][ty*8 + i];
            #pragma unroll
            for (int j = 0; j < 8; j++) b[j] = Ws[buf][k][tx*8 + j];
            #pragma unroll
            for (int i = 0; i < 8; i++)
                #pragma unroll
                for (int j = 0; j < 8; j++)
                    acc[i][j] += a[i] * b[j];
        }

        if (has_next) {
            const int nb = 1 - buf;
            As[nb][lk+0][lr] = a0.x; As[nb][lk+1][lr] = a0.y; As[nb][lk+2][lr] = a0.z; As[nb][lk+3][lr] = a0.w;
            As[nb][lk+4][lr] = a1.x; As[nb][lk+5][lr] = a1.y; As[nb][lk+6][lr] = a1.z; As[nb][lk+7][lr] = a1.w;
            Ws[nb][lk+0][lr] = w0.x; Ws[nb][lk+1][lr] = w0.y; Ws[nb][lk+2][lr] = w0.z; Ws[nb][lk+3][lr] = w0.w;
            Ws[nb][lk+4][lr] = w1.x; Ws[nb][lk+5][lr] = w1.y; Ws[nb][lk+6][lr] = w1.z; Ws[nb][lk+7][lr] = w1.w;
        }
        __syncthreads();
    }

    // vectorized epilogue: two float4 stores per row
    const int colv = col0 + tx*8;
    float4 bv0 = *(const float4*)&bias[colv];
    float4 bv1 = *(const float4*)&bias[colv + 4];
    #pragma unroll
    for (int i = 0; i < 8; i++) {
        int row = row0 + ty*8 + i;
        float4 v0, v1;
        v0.x = acc[i][0] + bv0.x; v0.y = acc[i][1] + bv0.y;
        v0.z = acc[i][2] + bv0.z; v0.w = acc[i][3] + bv0.w;
        v1.x = acc[i][4] + bv1.x; v1.y = acc[i][5] + bv1.y;
        v1.z = acc[i][6] + bv1.z; v1.w = acc[i][7] + bv1.w;
        if (ACT == 1) {
            v0.x = 1.0f/(1.0f+__expf(-v0.x)); v0.y = 1.0f/(1.0f+__expf(-v0.y));
            v0.z = 1.0f/(1.0f+__expf(-v0.z)); v0.w = 1.0f/(1.0f+__expf(-v0.w));
            v1.x = 1.0f/(1.0f+__expf(-v1.x)); v1.y = 1.0f/(1.0f+__expf(-v1.y));
            v1.z = 1.0f/(1.0f+__expf(-v1.z)); v1.w = 1.0f/(1.0f+__expf(-v1.w));
        }
        *(float4*)&C[(size_t)row * N + colv]     = v0;
        *(float4*)&C[(size_t)row * N + colv + 4] = v1;
    }
}

// ---------------------------------------------------------------------------
// RoPE in-place on (B, L, H, HD) layout. cos/sin are (1, L, HD), halves dup'd.
// ---------------------------------------------------------------------------
__global__ void rope_kernel(float* __restrict__ X,
                            const float* __restrict__ cosb,
                            const float* __restrict__ sinb) {
    int idx = blockIdx.x * blockDim.x + threadIdx.x;
    if (idx >= BN * LL * HH * (HD/2)) return;
    int d = idx & 31;
    int h = (idx >> 5) & (HH - 1);
    int l = (idx >> 9) & (LL - 1);
    int b = idx >> 20;
    size_t base = ((size_t)(b * LL + l) * DD) + h * HD;
    float x1 = X[base + d];
    float x2 = X[base + d + 32];
    float c = cosb[l * HD + d];
    float s = sinb[l * HD + d];
    X[base + d]      = x1 * c - x2 * s;
    X[base + d + 32] = x2 * c + x1 * s;
}

// ---------------------------------------------------------------------------
// Fused flash attention + gate:
//   for one (bh, 64-row q block): online-softmax over 32 k-tiles of 64,
//   O[b,q,h,:] = (softmax(QK^T*0.125 + mask) @ V) * G, all-masked rows -> 0.
// Mask is read as 32-bit words (covers both int32 and float32 encodings of
// the original bool array: nonzero bits <=> True).
// ---------------------------------------------------------------------------
#define FPAD 68
__global__ __launch_bounds__(256, 2)
void flash_kernel(const int* __restrict__ mask) {
    extern __shared__ float sm[];
    float* Qs = sm;                    // [64][FPAD]  Qs[d][q]
    float* Ks = sm + 64*FPAD;          // [64][FPAD]  Ks[d][k]
    float* Ps = sm + 2*64*FPAD;        // [64][FPAD]  Ps[k][q]
    float* Vs = sm + 3*64*FPAD;        // [64][FPAD]  Vs[k][d]

    const int tid = threadIdx.x;
    const int tx = tid & 15;
    const int ty = tid >> 4;
    const int bh = blockIdx.y;
    const int b = bh >> 4, h = bh & 15;
    const int q0 = blockIdx.x * 64;

    const float* Qb = g_Q + (size_t)b * LL * DD + h * HD;
    const float* Kb = g_K + (size_t)b * LL * DD + h * HD;
    const float* Vb = g_V + (size_t)b * LL * DD + h * HD;
    const int* mb = mask + b * LL;

    const int lr = tid >> 2;          // 0..63
    const int lc = tid & 3;           // 0..3

    // Load Q tile (once), transposed: Qs[d][row]
    #pragma unroll
    for (int c = 0; c < 4; c++) {
        int d0 = c * 16 + lc * 4;
        float4 v = *(const float4*)&Qb[(size_t)(q0 + lr) * DD + d0];
        Qs[(d0+0)*FPAD + lr] = v.x;
        Qs[(d0+1)*FPAD + lr] = v.y;
        Qs[(d0+2)*FPAD + lr] = v.z;
        Qs[(d0+3)*FPAD + lr] = v.w;
    }

    float m[4], l[4], acc[4][4];
    #pragma unroll
    for (int i = 0; i < 4; i++) {
        m[i] = -1e30f; l[i] = 0.0f;
        #pragma unroll
        for (int j = 0; j < 4; j++) acc[i][j] = 0.0f;
    }

    for (int kt = 0; kt < LL/64; kt++) {
        const int k0 = kt * 64;
        __syncthreads();   // prior iteration's reads of Ks/Vs/Ps complete
        // Load K tile transposed, V tile natural
        #pragma unroll
        for (int c = 0; c < 4; c++) {
            int d0 = c * 16 + lc * 4;
            float4 kv = *(const float4*)&Kb[(size_t)(k0 + lr) * DD + d0];
            Ks[(d0+0)*FPAD + lr] = kv.x;
            Ks[(d0+1)*FPAD + lr] = kv.y;
            Ks[(d0+2)*FPAD + lr] = kv.z;
            Ks[(d0+3)*FPAD + lr] = kv.w;
            float4 vv = *(const float4*)&Vb[(size_t)(k0 + lr) * DD + d0];
            Vs[lr*FPAD + d0+0] = vv.x;
            Vs[lr*FPAD + d0+1] = vv.y;
            Vs[lr*FPAD + d0+2] = vv.z;
            Vs[lr*FPAD + d0+3] = vv.w;
        }
        __syncthreads();

        // S = Q @ K^T  (thread: 4 q rows x 4 k cols)
        float s[4][4] = {};
        #pragma unroll
        for (int d = 0; d < 64; d++) {
            float a[4], bb[4];
            #pragma unroll
            for (int i = 0; i < 4; i++) a[i] = Qs[d*FPAD + ty*4 + i];
            #pragma unroll
            for (int j = 0; j < 4; j++) bb[j] = Ks[d*FPAD + tx*4 + j];
            #pragma unroll
            for (int i = 0; i < 4; i++)
                #pragma unroll
                for (int j = 0; j < 4; j++)
                    s[i][j] += a[i] * bb[j];
        }
        // scale + mask (mask word nonzero => padded/disallowed)
        #pragma unroll
        for (int j = 0; j < 4; j++) {
            bool pad = mb[k0 + tx*4 + j] != 0;
            #pragma unroll
            for (int i = 0; i < 4; i++)
                s[i][j] = pad ? -1e30f : s[i][j] * 0.125f;
        }

        // online softmax update
        float p[4][4];
        #pragma unroll
        for (int i = 0; i < 4; i++) {
            float tm = fmaxf(fmaxf(s[i][0], s[i][1]), fmaxf(s[i][2], s[i][3]));
            #pragma unroll
            for (int o = 8; o >= 1; o >>= 1)
                tm = fmaxf(tm, __shfl_xor_sync(0xffffffffu, tm, o));
            float mn = fmaxf(m[i], tm);
            float corr = __expf(m[i] - mn);
            float rs = 0.0f;
            #pragma unroll
            for (int j = 0; j < 4; j++) {
                p[i][j] = __expf(s[i][j] - mn);
                rs += p[i][j];
            }
            #pragma unroll
            for (int o = 8; o >= 1; o >>= 1)
                rs += __shfl_xor_sync(0xffffffffu, rs, o);
            l[i] = l[i] * corr + rs;
            m[i] = mn;
            #pragma unroll
            for (int j = 0; j < 4; j++) acc[i][j] *= corr;
        }

        // stage P (transposed: Ps[kcol][qrow])
        #pragma unroll
        for (int i = 0; i < 4; i++)
            #pragma unroll
            for (int j = 0; j < 4; j++)
                Ps[(tx*4 + j)*FPAD + ty*4 + i] = p[i][j];
        __syncthreads();

        // acc += P @ V  (thread: 4 q rows x 4 head dims = tx*4+j)
        #pragma unroll
        for (int kk = 0; kk < 64; kk++) {
            float a[4], bb[4];
            #pragma unroll
            for (int i = 0; i < 4; i++) a[i] = Ps[kk*FPAD + ty*4 + i];
            #pragma unroll
            for (int j = 0; j < 4; j++) bb[j] = Vs[kk*FPAD + tx*4 + j];
            #pragma unroll
            for (int i = 0; i < 4; i++)
                #pragma unroll
                for (int j = 0; j < 4; j++)
                    acc[i][j] += a[i] * bb[j];
        }
    }

    // epilogue: normalize, all-masked -> 0, apply gate (vectorized)
    #pragma unroll
    for (int i = 0; i < 4; i++) {
        int q = q0 + ty*4 + i;
        float inv = (m[i] < -1e29f) ? 0.0f : 1.0f / l[i];
        size_t oi = (size_t)(b * LL + q) * DD + h * HD + tx*4;
        float4 gv = *(const float4*)&g_G[oi];
        float4 ov;
        ov.x = acc[i][0] * inv * gv.x;
        ov.y = acc[i][1] * inv * gv.y;
        ov.z = acc[i][2] * inv * gv.z;
        ov.w = acc[i][3] * inv * gv.w;
        *(float4*)&g_O[oi] = ov;
    }
}

// ---------------------------------------------------------------------------
extern "C" void kernel_launch(void* const* d_in, const int* in_sizes, int n_in,
                              void* d_out, int out_size) {
    const float* query = (const float*)d_in[0];
    const float* key   = (const float*)d_in[1];
    const float* value = (const float*)d_in[2];
    const int*   mask  = (const int*)d_in[3];   // bool coerced to 32-bit by harness
    const float* rcos = (const float*)d_in[4];
    const float* rsin = (const float*)d_in[5];
    const float* Wq = (const float*)d_in[6];
    const float* bq = (const float*)d_in[7];
    const float* Wk = (const float*)d_in[8];
    const float* bk = (const float*)d_in[9];
    const float* Wv = (const float*)d_in[10];
    const float* bv = (const float*)d_in[11];
    const float* Wg = (const float*)d_in[12];
    const float* bg = (const float*)d_in[13];
    const float* Wo = (const float*)d_in[14];
    const float* bo = (const float*)d_in[15];
    float* out = (float*)d_out;

    void *pQ, *pK, *pV, *pG, *pO;
    cudaGetSymbolAddress(&pQ, g_Q);
    cudaGetSymbolAddress(&pK, g_K);
    cudaGetSymbolAddress(&pV, g_V);
    cudaGetSymbolAddress(&pG, g_G);
    cudaGetSymbolAddress(&pO, g_O);

    const int M = BN * LL;             // 4096
    dim3 blk(256);
    dim3 gproj(DD / 128, M / 128);     // 8 x 32

    gemm_bias_kernel<0><<<gproj, blk>>>(query, Wq, bq, (float*)pQ, M, DD, DD);
    gemm_bias_kernel<0><<<gproj, blk>>>(key,   Wk, bk, (float*)pK, M, DD, DD);
    gemm_bias_kernel<0><<<gproj, blk>>>(value, Wv, bv, (float*)pV, M, DD, DD);
    gemm_bias_kernel<1><<<gproj, blk>>>(query, Wg, bg, (float*)pG, M, DD, DD);

    int nrope = BN * LL * HH * (HD / 2);
    rope_kernel<<<nrope / 256, 256>>>((float*)pQ, rcos, rsin);
    rope_kernel<<<nrope / 256, 256>>>((float*)pK, rcos, rsin);

    int flash_smem = 4 * 64 * FPAD * sizeof(float);   // 69,632 B
    cudaFuncSetAttribute(flash_kernel,
                         cudaFuncAttributeMaxDynamicSharedMemorySize,
                         flash_smem);
    flash_kernel<<<dim3(LL / 64, BH), blk, flash_smem>>>(mask);

    gemm_bias_kernel<0><<<gproj, blk>>>((const float*)pO, Wo, bo, out, M, DD, DD);
}

// round 13
// speedup vs baseline: 1.3670x; 1.3670x over previous
#include <cuda_runtime.h>
#include <cuda_bf16.h>
#include <mma.h>
#include <math.h>

using namespace nvcuda;

#define BN 2
#define LL 2048
#define DD 1024
#define HH 16
#define HD 64
#define BH (BN*HH)

// Static scratch (runtime allocation is forbidden).
__device__ float g_Q[BN*LL*DD];
__device__ float g_K[BN*LL*DD];
__device__ float g_V[BN*LL*DD];
__device__ float g_G[BN*LL*DD];
__device__ float g_O[BN*LL*DD];

// ---------------------------------------------------------------------------
// bf16x3 split-precision WMMA GEMM: C[M,N] = A[M,K] @ W[N,K]^T + bias[N].
// fp32 operands split as x = hi + lo (both bf16, round-nearest); product
// approximated by Ahi*Whi + Ahi*Wlo + Alo*Whi (fp32 accum). Dropped lo*lo
// term is ~2^-18 relative.
// CTA tile 128x128, BK=32, 8 warps (4 along M x 2 along N), warp tile 32x64.
// Dynamic smem: compute phase 4 x [128][LDA] bf16 = 40960B; epilogue reuses
// it as 8 x [32][64] float staging = 65536B.
// ---------------------------------------------------------------------------
#define LDA 40   // bf16 leading dim (80B, multiple of 16B as wmma requires)

template<int ACT>
__global__ void gemm_bias_kernel(const float* __restrict__ A,
                                 const float* __restrict__ W,
                                 const float* __restrict__ bias,
                                 float* __restrict__ C,
                                 int M, int N, int K) {
    extern __shared__ char smraw[];
    __nv_bfloat16* Ahi = (__nv_bfloat16*)smraw;          // [128][LDA]
    __nv_bfloat16* Alo = Ahi + 128*LDA;
    __nv_bfloat16* Whi = Alo + 128*LDA;
    __nv_bfloat16* Wlo = Whi + 128*LDA;

    const int tid = threadIdx.x;
    const int wid = tid >> 5;
    const int lane = tid & 31;
    const int warp_m = wid & 3;        // 0..3 (M direction)
    const int warp_n = wid >> 2;       // 0..1 (N direction)
    const int row0 = blockIdx.y * 128;
    const int col0 = blockIdx.x * 128;

    // loader mapping: 2 threads per row, 16 k-elements each
    const int lrow = tid >> 1;         // 0..127
    const int lks  = (tid & 1) * 16;   // 0 or 16

    wmma::fragment<wmma::accumulator, 16,16,16, float> acc[2][4];
    #pragma unroll
    for (int i = 0; i < 2; i++)
        #pragma unroll
        for (int j = 0; j < 4; j++)
            wmma::fill_fragment(acc[i][j], 0.0f);

    for (int k0 = 0; k0 < K; k0 += 32) {
        __syncthreads();   // prior iteration's fragment loads complete

        // load + split A slab [128][32]
        {
            const float* src = &A[(size_t)(row0 + lrow) * K + k0 + lks];
            #pragma unroll
            for (int q = 0; q < 4; q++) {
                float4 v = *(const float4*)&src[q*4];
                float xs[4] = {v.x, v.y, v.z, v.w};
                #pragma unroll
                for (int e = 0; e < 4; e++) {
                    __nv_bfloat16 hb = __float2bfloat16(xs[e]);
                    Ahi[lrow*LDA + lks + q*4 + e] = hb;
                    Alo[lrow*LDA + lks + q*4 + e] =
                        __float2bfloat16(xs[e] - __bfloat162float(hb));
                }
            }
            const float* wsrc = &W[(size_t)(col0 + lrow) * K + k0 + lks];
            #pragma unroll
            for (int q = 0; q < 4; q++) {
                float4 v = *(const float4*)&wsrc[q*4];
                float xs[4] = {v.x, v.y, v.z, v.w};
                #pragma unroll
                for (int e = 0; e < 4; e++) {
                    __nv_bfloat16 hb = __float2bfloat16(xs[e]);
                    Whi[lrow*LDA + lks + q*4 + e] = hb;
                    Wlo[lrow*LDA + lks + q*4 + e] =
                        __float2bfloat16(xs[e] - __bfloat162float(hb));
                }
            }
        }
        __syncthreads();

        #pragma unroll
        for (int ks = 0; ks < 32; ks += 16) {
            wmma::fragment<wmma::matrix_a, 16,16,16, __nv_bfloat16, wmma::row_major> ahi[2], alo[2];
            wmma::fragment<wmma::matrix_b, 16,16,16, __nv_bfloat16, wmma::col_major> whi[4], wlo[4];
            #pragma unroll
            for (int i = 0; i < 2; i++) {
                int r = warp_m*32 + i*16;
                wmma::load_matrix_sync(ahi[i], &Ahi[r*LDA + ks], LDA);
                wmma::load_matrix_sync(alo[i], &Alo[r*LDA + ks], LDA);
            }
            #pragma unroll
            for (int j = 0; j < 4; j++) {
                int c = warp_n*64 + j*16;
                wmma::load_matrix_sync(whi[j], &Whi[c*LDA + ks], LDA);
                wmma::load_matrix_sync(wlo[j], &Wlo[c*LDA + ks], LDA);
            }
            #pragma unroll
            for (int i = 0; i < 2; i++)
                #pragma unroll
                for (int j = 0; j < 4; j++) {
                    wmma::mma_sync(acc[i][j], ahi[i], whi[j], acc[i][j]);
                    wmma::mma_sync(acc[i][j], ahi[i], wlo[j], acc[i][j]);
                    wmma::mma_sync(acc[i][j], alo[i], whi[j], acc[i][j]);
                }
        }
    }

    // epilogue: stage accumulators in smem (repurposed), add bias, activate
    __syncthreads();   // everyone done with bf16 tiles
    float* stage = (float*)smraw + wid * (32*64);   // 8KB per warp
    #pragma unroll
    for (int i = 0; i < 2; i++)
        #pragma unroll
        for (int j = 0; j < 4; j++)
            wmma::store_matrix_sync(&stage[i*16*64 + j*16], acc[i][j], 64,
                                    wmma::mem_row_major);
    __syncwarp();

    const int wrow0 = row0 + warp_m*32;
    const int wcol0 = col0 + warp_n*64;
    #pragma unroll
    for (int it = 0; it < 16; it++) {
        int f = it*32 + lane;          // float4 index 0..511
        int r = f >> 4;                // /16 rows of 64 floats
        int c = (f & 15) * 4;
        float4 v = *(float4*)&stage[r*64 + c];
        float4 bv = *(const float4*)&bias[wcol0 + c];
        v.x += bv.x; v.y += bv.y; v.z += bv.z; v.w += bv.w;
        if (ACT == 1) {
            v.x = 1.0f/(1.0f+__expf(-v.x)); v.y = 1.0f/(1.0f+__expf(-v.y));
            v.z = 1.0f/(1.0f+__expf(-v.z)); v.w = 1.0f/(1.0f+__expf(-v.w));
        }
        *(float4*)&C[(size_t)(wrow0 + r) * N + wcol0 + c] = v;
    }
}

// ---------------------------------------------------------------------------
// RoPE in-place on (B, L, H, HD) layout. cos/sin are (1, L, HD), halves dup'd.
// ---------------------------------------------------------------------------
__global__ void rope_kernel(float* __restrict__ X,
                            const float* __restrict__ cosb,
                            const float* __restrict__ sinb) {
    int idx = blockIdx.x * blockDim.x + threadIdx.x;
    if (idx >= BN * LL * HH * (HD/2)) return;
    int d = idx & 31;
    int h = (idx >> 5) & (HH - 1);
    int l = (idx >> 9) & (LL - 1);
    int b = idx >> 20;
    size_t base = ((size_t)(b * LL + l) * DD) + h * HD;
    float x1 = X[base + d];
    float x2 = X[base + d + 32];
    float c = cosb[l * HD + d];
    float s = sinb[l * HD + d];
    X[base + d]      = x1 * c - x2 * s;
    X[base + d + 32] = x2 * c + x1 * s;
}

// ---------------------------------------------------------------------------
// Fused flash attention + gate (fp32 SIMT; unchanged from R11-passing build).
// ---------------------------------------------------------------------------
#define FPAD 68
__global__ __launch_bounds__(256, 2)
void flash_kernel(const int* __restrict__ mask) {
    extern __shared__ float sm[];
    float* Qs = sm;                    // [64][FPAD]  Qs[d][q]
    float* Ks = sm + 64*FPAD;          // [64][FPAD]  Ks[d][k]
    float* Ps = sm + 2*64*FPAD;        // [64][FPAD]  Ps[k][q]
    float* Vs = sm + 3*64*FPAD;        // [64][FPAD]  Vs[k][d]

    const int tid = threadIdx.x;
    const int tx = tid & 15;
    const int ty = tid >> 4;
    const int bh = blockIdx.y;
    const int b = bh >> 4, h = bh & 15;
    const int q0 = blockIdx.x * 64;

    const float* Qb = g_Q + (size_t)b * LL * DD + h * HD;
    const float* Kb = g_K + (size_t)b * LL * DD + h * HD;
    const float* Vb = g_V + (size_t)b * LL * DD + h * HD;
    const int* mb = mask + b * LL;

    const int lr = tid >> 2;          // 0..63
    const int lc = tid & 3;           // 0..3

    #pragma unroll
    for (int c = 0; c < 4; c++) {
        int d0 = c * 16 + lc * 4;
        float4 v = *(const float4*)&Qb[(size_t)(q0 + lr) * DD + d0];
        Qs[(d0+0)*FPAD + lr] = v.x;
        Qs[(d0+1)*FPAD + lr] = v.y;
        Qs[(d0+2)*FPAD + lr] = v.z;
        Qs[(d0+3)*FPAD + lr] = v.w;
    }

    float m[4], l[4], acc[4][4];
    #pragma unroll
    for (int i = 0; i < 4; i++) {
        m[i] = -1e30f; l[i] = 0.0f;
        #pragma unroll
        for (int j = 0; j < 4; j++) acc[i][j] = 0.0f;
    }

    for (int kt = 0; kt < LL/64; kt++) {
        const int k0 = kt * 64;
        __syncthreads();
        #pragma unroll
        for (int c = 0; c < 4; c++) {
            int d0 = c * 16 + lc * 4;
            float4 kv = *(const float4*)&Kb[(size_t)(k0 + lr) * DD + d0];
            Ks[(d0+0)*FPAD + lr] = kv.x;
            Ks[(d0+1)*FPAD + lr] = kv.y;
            Ks[(d0+2)*FPAD + lr] = kv.z;
            Ks[(d0+3)*FPAD + lr] = kv.w;
            float4 vv = *(const float4*)&Vb[(size_t)(k0 + lr) * DD + d0];
            Vs[lr*FPAD + d0+0] = vv.x;
            Vs[lr*FPAD + d0+1] = vv.y;
            Vs[lr*FPAD + d0+2] = vv.z;
            Vs[lr*FPAD + d0+3] = vv.w;
        }
        __syncthreads();

        float s[4][4] = {};
        #pragma unroll
        for (int d = 0; d < 64; d++) {
            float a[4], bb[4];
            #pragma unroll
            for (int i = 0; i < 4; i++) a[i] = Qs[d*FPAD + ty*4 + i];
            #pragma unroll
            for (int j = 0; j < 4; j++) bb[j] = Ks[d*FPAD + tx*4 + j];
            #pragma unroll
            for (int i = 0; i < 4; i++)
                #pragma unroll
                for (int j = 0; j < 4; j++)
                    s[i][j] += a[i] * bb[j];
        }
        #pragma unroll
        for (int j = 0; j < 4; j++) {
            bool pad = mb[k0 + tx*4 + j] != 0;
            #pragma unroll
            for (int i = 0; i < 4; i++)
                s[i][j] = pad ? -1e30f : s[i][j] * 0.125f;
        }

        float p[4][4];
        #pragma unroll
        for (int i = 0; i < 4; i++) {
            float tm = fmaxf(fmaxf(s[i][0], s[i][1]), fmaxf(s[i][2], s[i][3]));
            #pragma unroll
            for (int o = 8; o >= 1; o >>= 1)
                tm = fmaxf(tm, __shfl_xor_sync(0xffffffffu, tm, o));
            float mn = fmaxf(m[i], tm);
            float corr = __expf(m[i] - mn);
            float rs = 0.0f;
            #pragma unroll
            for (int j = 0; j < 4; j++) {
                p[i][j] = __expf(s[i][j] - mn);
                rs += p[i][j];
            }
            #pragma unroll
            for (int o = 8; o >= 1; o >>= 1)
                rs += __shfl_xor_sync(0xffffffffu, rs, o);
            l[i] = l[i] * corr + rs;
            m[i] = mn;
            #pragma unroll
            for (int j = 0; j < 4; j++) acc[i][j] *= corr;
        }

        #pragma unroll
        for (int i = 0; i < 4; i++)
            #pragma unroll
            for (int j = 0; j < 4; j++)
                Ps[(tx*4 + j)*FPAD + ty*4 + i] = p[i][j];
        __syncthreads();

        #pragma unroll
        for (int kk = 0; kk < 64; kk++) {
            float a[4], bb[4];
            #pragma unroll
            for (int i = 0; i < 4; i++) a[i] = Ps[kk*FPAD + ty*4 + i];
            #pragma unroll
            for (int j = 0; j < 4; j++) bb[j] = Vs[kk*FPAD + tx*4 + j];
            #pragma unroll
            for (int i = 0; i < 4; i++)
                #pragma unroll
                for (int j = 0; j < 4; j++)
                    acc[i][j] += a[i] * bb[j];
        }
    }

    #pragma unroll
    for (int i = 0; i < 4; i++) {
        int q = q0 + ty*4 + i;
        float inv = (m[i] < -1e29f) ? 0.0f : 1.0f / l[i];
        size_t oi = (size_t)(b * LL + q) * DD + h * HD + tx*4;
        float4 gv = *(const float4*)&g_G[oi];
        float4 ov;
        ov.x = acc[i][0] * inv * gv.x;
        ov.y = acc[i][1] * inv * gv.y;
        ov.z = acc[i][2] * inv * gv.z;
        ov.w = acc[i][3] * inv * gv.w;
        *(float4*)&g_O[oi] = ov;
    }
}

// ---------------------------------------------------------------------------
extern "C" void kernel_launch(void* const* d_in, const int* in_sizes, int n_in,
                              void* d_out, int out_size) {
    const float* query = (const float*)d_in[0];
    const float* key   = (const float*)d_in[1];
    const float* value = (const float*)d_in[2];
    const int*   mask  = (const int*)d_in[3];   // bool coerced to 32-bit by harness
    const float* rcos = (const float*)d_in[4];
    const float* rsin = (const float*)d_in[5];
    const float* Wq = (const float*)d_in[6];
    const float* bq = (const float*)d_in[7];
    const float* Wk = (const float*)d_in[8];
    const float* bk = (const float*)d_in[9];
    const float* Wv = (const float*)d_in[10];
    const float* bv = (const float*)d_in[11];
    const float* Wg = (const float*)d_in[12];
    const float* bg = (const float*)d_in[13];
    const float* Wo = (const float*)d_in[14];
    const float* bo = (const float*)d_in[15];
    float* out = (float*)d_out;

    void *pQ, *pK, *pV, *pG, *pO;
    cudaGetSymbolAddress(&pQ, g_Q);
    cudaGetSymbolAddress(&pK, g_K);
    cudaGetSymbolAddress(&pV, g_V);
    cudaGetSymbolAddress(&pG, g_G);
    cudaGetSymbolAddress(&pO, g_O);

    const int M = BN * LL;             // 4096
    dim3 blk(256);
    dim3 gproj(DD / 128, M / 128);     // 8 x 32

    const int gemm_smem = 65536;       // max(compute 40960, staging 65536)
    cudaFuncSetAttribute(gemm_bias_kernel<0>,
                         cudaFuncAttributeMaxDynamicSharedMemorySize, gemm_smem);
    cudaFuncSetAttribute(gemm_bias_kernel<1>,
                         cudaFuncAttributeMaxDynamicSharedMemorySize, gemm_smem);

    gemm_bias_kernel<0><<<gproj, blk, gemm_smem>>>(query, Wq, bq, (float*)pQ, M, DD, DD);
    gemm_bias_kernel<0><<<gproj, blk, gemm_smem>>>(key,   Wk, bk, (float*)pK, M, DD, DD);
    gemm_bias_kernel<0><<<gproj, blk, gemm_smem>>>(value, Wv, bv, (float*)pV, M, DD, DD);
    gemm_bias_kernel<1><<<gproj, blk, gemm_smem>>>(query, Wg, bg, (float*)pG, M, DD, DD);

    int nrope = BN * LL * HH * (HD / 2);
    rope_kernel<<<nrope / 256, 256>>>((float*)pQ, rcos, rsin);
    rope_kernel<<<nrope / 256, 256>>>((float*)pK, rcos, rsin);

    int flash_smem = 4 * 64 * FPAD * sizeof(float);   // 69,632 B
    cudaFuncSetAttribute(flash_kernel,
                         cudaFuncAttributeMaxDynamicSharedMemorySize,
                         flash_smem);
    flash_kernel<<<dim3(LL / 64, BH), blk, flash_smem>>>(mask);

    gemm_bias_kernel<0><<<gproj, blk, gemm_smem>>>((const float*)pO, Wo, bo, out, M, DD, DD);
}

// round 14
// speedup vs baseline: 1.4827x; 1.0846x over previous
#include <cuda_runtime.h>
#include <cuda_bf16.h>
#include <mma.h>
#include <math.h>

using namespace nvcuda;

#define BN 2
#define LL 2048
#define DD 1024
#define HH 16
#define HD 64
#define BH (BN*HH)

// Static scratch (runtime allocation is forbidden).
__device__ float g_Q[BN*LL*DD];
__device__ float g_K[BN*LL*DD];
__device__ float g_V[BN*LL*DD];
__device__ float g_G[BN*LL*DD];
__device__ float g_O[BN*LL*DD];

// ---------------------------------------------------------------------------
// bf16x3 split-precision WMMA GEMM (unchanged from R13-passing build).
// ---------------------------------------------------------------------------
#define LDA 40   // bf16 leading dim (80B, multiple of 16B as wmma requires)

template<int ACT>
__global__ void gemm_bias_kernel(const float* __restrict__ A,
                                 const float* __restrict__ W,
                                 const float* __restrict__ bias,
                                 float* __restrict__ C,
                                 int M, int N, int K) {
    extern __shared__ char smraw[];
    __nv_bfloat16* Ahi = (__nv_bfloat16*)smraw;          // [128][LDA]
    __nv_bfloat16* Alo = Ahi + 128*LDA;
    __nv_bfloat16* Whi = Alo + 128*LDA;
    __nv_bfloat16* Wlo = Whi + 128*LDA;

    const int tid = threadIdx.x;
    const int wid = tid >> 5;
    const int lane = tid & 31;
    const int warp_m = wid & 3;
    const int warp_n = wid >> 2;
    const int row0 = blockIdx.y * 128;
    const int col0 = blockIdx.x * 128;

    const int lrow = tid >> 1;
    const int lks  = (tid & 1) * 16;

    wmma::fragment<wmma::accumulator, 16,16,16, float> acc[2][4];
    #pragma unroll
    for (int i = 0; i < 2; i++)
        #pragma unroll
        for (int j = 0; j < 4; j++)
            wmma::fill_fragment(acc[i][j], 0.0f);

    for (int k0 = 0; k0 < K; k0 += 32) {
        __syncthreads();
        {
            const float* src = &A[(size_t)(row0 + lrow) * K + k0 + lks];
            #pragma unroll
            for (int q = 0; q < 4; q++) {
                float4 v = *(const float4*)&src[q*4];
                float xs[4] = {v.x, v.y, v.z, v.w};
                #pragma unroll
                for (int e = 0; e < 4; e++) {
                    __nv_bfloat16 hb = __float2bfloat16(xs[e]);
                    Ahi[lrow*LDA + lks + q*4 + e] = hb;
                    Alo[lrow*LDA + lks + q*4 + e] =
                        __float2bfloat16(xs[e] - __bfloat162float(hb));
                }
            }
            const float* wsrc = &W[(size_t)(col0 + lrow) * K + k0 + lks];
            #pragma unroll
            for (int q = 0; q < 4; q++) {
                float4 v = *(const float4*)&wsrc[q*4];
                float xs[4] = {v.x, v.y, v.z, v.w};
                #pragma unroll
                for (int e = 0; e < 4; e++) {
                    __nv_bfloat16 hb = __float2bfloat16(xs[e]);
                    Whi[lrow*LDA + lks + q*4 + e] = hb;
                    Wlo[lrow*LDA + lks + q*4 + e] =
                        __float2bfloat16(xs[e] - __bfloat162float(hb));
                }
            }
        }
        __syncthreads();

        #pragma unroll
        for (int ks = 0; ks < 32; ks += 16) {
            wmma::fragment<wmma::matrix_a, 16,16,16, __nv_bfloat16, wmma::row_major> ahi[2], alo[2];
            wmma::fragment<wmma::matrix_b, 16,16,16, __nv_bfloat16, wmma::col_major> whi[4], wlo[4];
            #pragma unroll
            for (int i = 0; i < 2; i++) {
                int r = warp_m*32 + i*16;
                wmma::load_matrix_sync(ahi[i], &Ahi[r*LDA + ks], LDA);
                wmma::load_matrix_sync(alo[i], &Alo[r*LDA + ks], LDA);
            }
            #pragma unroll
            for (int j = 0; j < 4; j++) {
                int c = warp_n*64 + j*16;
                wmma::load_matrix_sync(whi[j], &Whi[c*LDA + ks], LDA);
                wmma::load_matrix_sync(wlo[j], &Wlo[c*LDA + ks], LDA);
            }
            #pragma unroll
            for (int i = 0; i < 2; i++)
                #pragma unroll
                for (int j = 0; j < 4; j++) {
                    wmma::mma_sync(acc[i][j], ahi[i], whi[j], acc[i][j]);
                    wmma::mma_sync(acc[i][j], ahi[i], wlo[j], acc[i][j]);
                    wmma::mma_sync(acc[i][j], alo[i], whi[j], acc[i][j]);
                }
        }
    }

    __syncthreads();
    float* stage = (float*)smraw + wid * (32*64);
    #pragma unroll
    for (int i = 0; i < 2; i++)
        #pragma unroll
        for (int j = 0; j < 4; j++)
            wmma::store_matrix_sync(&stage[i*16*64 + j*16], acc[i][j], 64,
                                    wmma::mem_row_major);
    __syncwarp();

    const int wrow0 = row0 + warp_m*32;
    const int wcol0 = col0 + warp_n*64;
    #pragma unroll
    for (int it = 0; it < 16; it++) {
        int f = it*32 + lane;
        int r = f >> 4;
        int c = (f & 15) * 4;
        float4 v = *(float4*)&stage[r*64 + c];
        float4 bv = *(const float4*)&bias[wcol0 + c];
        v.x += bv.x; v.y += bv.y; v.z += bv.z; v.w += bv.w;
        if (ACT == 1) {
            v.x = 1.0f/(1.0f+__expf(-v.x)); v.y = 1.0f/(1.0f+__expf(-v.y));
            v.z = 1.0f/(1.0f+__expf(-v.z)); v.w = 1.0f/(1.0f+__expf(-v.w));
        }
        *(float4*)&C[(size_t)(wrow0 + r) * N + wcol0 + c] = v;
    }
}

// ---------------------------------------------------------------------------
// RoPE in-place on (B, L, H, HD) layout.
// ---------------------------------------------------------------------------
__global__ void rope_kernel(float* __restrict__ X,
                            const float* __restrict__ cosb,
                            const float* __restrict__ sinb) {
    int idx = blockIdx.x * blockDim.x + threadIdx.x;
    if (idx >= BN * LL * HH * (HD/2)) return;
    int d = idx & 31;
    int h = (idx >> 5) & (HH - 1);
    int l = (idx >> 9) & (LL - 1);
    int b = idx >> 20;
    size_t base = ((size_t)(b * LL + l) * DD) + h * HD;
    float x1 = X[base + d];
    float x2 = X[base + d + 32];
    float c = cosb[l * HD + d];
    float s = sinb[l * HD + d];
    X[base + d]      = x1 * c - x2 * s;
    X[base + d + 32] = x2 * c + x1 * s;
}

// ---------------------------------------------------------------------------
// Flash attention with bf16x3 WMMA matmuls + fp32 softmax/state in smem.
// One CTA = 64 q-rows of one (b,h). 8 warps: warp_m=wid&3 (16 rows each),
// warp_n=wid>>2 (32 cols each). S and O tiles live in fp32 smem; P/Q/K/V
// are hi+lo bf16 splits (3-term products, lo*lo dropped ~2^-16).
// ---------------------------------------------------------------------------
#define FLD 72     // bf16 tile leading dim (mult of 8)
#define SLD 68     // fp32 staging leading dim (mult of 4)
// smem byte offsets (all 256-aligned)
#define SM_QHI 0
#define SM_QLO 9216
#define SM_KHI 18432
#define SM_KLO 27648
#define SM_VHI 36864
#define SM_VLO 46080
#define SM_PHI 55296
#define SM_PLO 64512
#define SM_SF  73728
#define SM_OF  91136
#define SM_M   108544
#define SM_L   108800
#define FLASH_SMEM 109056

__global__ void flash_kernel(const int* __restrict__ mask) {
    extern __shared__ char smraw[];
    __nv_bfloat16* Qhi = (__nv_bfloat16*)(smraw + SM_QHI);
    __nv_bfloat16* Qlo = (__nv_bfloat16*)(smraw + SM_QLO);
    __nv_bfloat16* Khi = (__nv_bfloat16*)(smraw + SM_KHI);
    __nv_bfloat16* Klo = (__nv_bfloat16*)(smraw + SM_KLO);
    __nv_bfloat16* Vhi = (__nv_bfloat16*)(smraw + SM_VHI);
    __nv_bfloat16* Vlo = (__nv_bfloat16*)(smraw + SM_VLO);
    __nv_bfloat16* Phi = (__nv_bfloat16*)(smraw + SM_PHI);
    __nv_bfloat16* Plo = (__nv_bfloat16*)(smraw + SM_PLO);
    float* Sf = (float*)(smraw + SM_SF);
    float* Of = (float*)(smraw + SM_OF);
    float* Ms = (float*)(smraw + SM_M);
    float* Ls = (float*)(smraw + SM_L);

    const int tid = threadIdx.x;
    const int wid = tid >> 5;
    const int warp_m = wid & 3;
    const int warp_n = wid >> 2;
    const int r = tid >> 2;        // 0..63 (row ownership for loads/softmax)
    const int quad = tid & 3;      // 4 threads per row
    const int c0 = quad * 16;

    const int bh = blockIdx.y;
    const int b = bh >> 4, h = bh & 15;
    const int q0 = blockIdx.x * 64;

    // load + split Q tile [64 q][64 d]
    {
        const float* src = g_Q + (size_t)(b*LL + q0 + r)*DD + h*HD + c0;
        #pragma unroll
        for (int q = 0; q < 4; q++) {
            float4 v = *(const float4*)&src[q*4];
            float xs[4] = {v.x, v.y, v.z, v.w};
            #pragma unroll
            for (int e = 0; e < 4; e++) {
                __nv_bfloat16 hb = __float2bfloat16(xs[e]);
                Qhi[r*FLD + c0 + q*4 + e] = hb;
                Qlo[r*FLD + c0 + q*4 + e] =
                    __float2bfloat16(xs[e] - __bfloat162float(hb));
            }
        }
        #pragma unroll
        for (int q = 0; q < 4; q++)
            *(float4*)&Of[r*SLD + c0 + q*4] = make_float4(0.f,0.f,0.f,0.f);
        if (quad == 0) { Ms[r] = -1e30f; Ls[r] = 0.0f; }
    }
    __syncthreads();

    for (int kt = 0; kt < LL/64; kt++) {
        const int k0 = kt * 64;

        // load + split K and V tiles [64 k][64 d]
        {
            const float* ksrc = g_K + (size_t)(b*LL + k0 + r)*DD + h*HD + c0;
            const float* vsrc = g_V + (size_t)(b*LL + k0 + r)*DD + h*HD + c0;
            #pragma unroll
            for (int q = 0; q < 4; q++) {
                float4 kv = *(const float4*)&ksrc[q*4];
                float4 vv = *(const float4*)&vsrc[q*4];
                float ka[4] = {kv.x, kv.y, kv.z, kv.w};
                float va[4] = {vv.x, vv.y, vv.z, vv.w};
                #pragma unroll
                for (int e = 0; e < 4; e++) {
                    __nv_bfloat16 hb = __float2bfloat16(ka[e]);
                    Khi[r*FLD + c0 + q*4 + e] = hb;
                    Klo[r*FLD + c0 + q*4 + e] =
                        __float2bfloat16(ka[e] - __bfloat162float(hb));
                    __nv_bfloat16 vb = __float2bfloat16(va[e]);
                    Vhi[r*FLD + c0 + q*4 + e] = vb;
                    Vlo[r*FLD + c0 + q*4 + e] =
                        __float2bfloat16(va[e] - __bfloat162float(vb));
                }
            }
        }
        __syncthreads();

        // S = Q @ K^T  (bf16x3 wmma) -> Sf
        {
            wmma::fragment<wmma::accumulator,16,16,16,float> acc[2];
            wmma::fill_fragment(acc[0], 0.0f);
            wmma::fill_fragment(acc[1], 0.0f);
            const int row0 = warp_m * 16;
            #pragma unroll
            for (int ks = 0; ks < 64; ks += 16) {
                wmma::fragment<wmma::matrix_a,16,16,16,__nv_bfloat16,wmma::row_major> ah, al;
                wmma::load_matrix_sync(ah, &Qhi[row0*FLD + ks], FLD);
                wmma::load_matrix_sync(al, &Qlo[row0*FLD + ks], FLD);
                #pragma unroll
                for (int j = 0; j < 2; j++) {
                    const int col0 = warp_n*32 + j*16;
                    wmma::fragment<wmma::matrix_b,16,16,16,__nv_bfloat16,wmma::col_major> bh_, bl_;
                    wmma::load_matrix_sync(bh_, &Khi[col0*FLD + ks], FLD);
                    wmma::load_matrix_sync(bl_, &Klo[col0*FLD + ks], FLD);
                    wmma::mma_sync(acc[j], ah, bh_, acc[j]);
                    wmma::mma_sync(acc[j], ah, bl_, acc[j]);
                    wmma::mma_sync(acc[j], al, bh_, acc[j]);
                }
            }
            #pragma unroll
            for (int j = 0; j < 2; j++)
                wmma::store_matrix_sync(&Sf[warp_m*16*SLD + warp_n*32 + j*16],
                                        acc[j], SLD, wmma::mem_row_major);
        }
        __syncthreads();

        // softmax (fp32): mask, online max/sum, write P split, rescale Of
        {
            float s[16];
            #pragma unroll
            for (int q = 0; q < 4; q++) {
                float4 v = *(float4*)&Sf[r*SLD + c0 + q*4];
                s[q*4+0] = v.x; s[q*4+1] = v.y; s[q*4+2] = v.z; s[q*4+3] = v.w;
            }
            const int4* mp = (const int4*)&mask[b*LL + k0 + c0];
            #pragma unroll
            for (int q = 0; q < 4; q++) {
                int4 mv = mp[q];
                if (mv.x) s[q*4+0] = -1e30f; else s[q*4+0] *= 0.125f;
                if (mv.y) s[q*4+1] = -1e30f; else s[q*4+1] *= 0.125f;
                if (mv.z) s[q*4+2] = -1e30f; else s[q*4+2] *= 0.125f;
                if (mv.w) s[q*4+3] = -1e30f; else s[q*4+3] *= 0.125f;
            }
            float tmax = s[0];
            #pragma unroll
            for (int e = 1; e < 16; e++) tmax = fmaxf(tmax, s[e]);
            tmax = fmaxf(tmax, __shfl_xor_sync(0xffffffffu, tmax, 1));
            tmax = fmaxf(tmax, __shfl_xor_sync(0xffffffffu, tmax, 2));
            float mold = Ms[r];
            float mn = fmaxf(mold, tmax);
            float corr = __expf(mold - mn);
            float rs = 0.0f;
            #pragma unroll
            for (int e = 0; e < 16; e++) { s[e] = __expf(s[e] - mn); rs += s[e]; }
            rs += __shfl_xor_sync(0xffffffffu, rs, 1);
            rs += __shfl_xor_sync(0xffffffffu, rs, 2);
            #pragma unroll
            for (int e = 0; e < 16; e++) {
                __nv_bfloat16 hb = __float2bfloat16(s[e]);
                Phi[r*FLD + c0 + e] = hb;
                Plo[r*FLD + c0 + e] = __float2bfloat16(s[e] - __bfloat162float(hb));
            }
            #pragma unroll
            for (int q = 0; q < 4; q++) {
                float4 o = *(float4*)&Of[r*SLD + c0 + q*4];
                o.x *= corr; o.y *= corr; o.z *= corr; o.w *= corr;
                *(float4*)&Of[r*SLD + c0 + q*4] = o;
            }
            if (quad == 0) { Ms[r] = mn; Ls[r] = Ls[r]*corr + rs; }
        }
        __syncthreads();

        // PV = P @ V (bf16x3 wmma) -> Sf staging
        {
            wmma::fragment<wmma::accumulator,16,16,16,float> acc[2];
            wmma::fill_fragment(acc[0], 0.0f);
            wmma::fill_fragment(acc[1], 0.0f);
            const int row0 = warp_m * 16;
            #pragma unroll
            for (int ks = 0; ks < 64; ks += 16) {
                wmma::fragment<wmma::matrix_a,16,16,16,__nv_bfloat16,wmma::row_major> ah, al;
                wmma::load_matrix_sync(ah, &Phi[row0*FLD + ks], FLD);
                wmma::load_matrix_sync(al, &Plo[row0*FLD + ks], FLD);
                #pragma unroll
                for (int j = 0; j < 2; j++) {
                    const int col0 = warp_n*32 + j*16;
                    wmma::fragment<wmma::matrix_b,16,16,16,__nv_bfloat16,wmma::row_major> bh_, bl_;
                    wmma::load_matrix_sync(bh_, &Vhi[ks*FLD + col0], FLD);
                    wmma::load_matrix_sync(bl_, &Vlo[ks*FLD + col0], FLD);
                    wmma::mma_sync(acc[j], ah, bh_, acc[j]);
                    wmma::mma_sync(acc[j], ah, bl_, acc[j]);
                    wmma::mma_sync(acc[j], al, bh_, acc[j]);
                }
            }
            #pragma unroll
            for (int j = 0; j < 2; j++)
                wmma::store_matrix_sync(&Sf[warp_m*16*SLD + warp_n*32 + j*16],
                                        acc[j], SLD, wmma::mem_row_major);
        }
        __syncthreads();

        // Of += PV tile
        #pragma unroll
        for (int q = 0; q < 4; q++) {
            float4 o = *(float4*)&Of[r*SLD + c0 + q*4];
            float4 a = *(float4*)&Sf[r*SLD + c0 + q*4];
            o.x += a.x; o.y += a.y; o.z += a.z; o.w += a.w;
            *(float4*)&Of[r*SLD + c0 + q*4] = o;
        }
        __syncthreads();
    }

    // epilogue: normalize, all-masked -> 0, gate, store
    {
        float inv = (Ms[r] < -1e29f) ? 0.0f : 1.0f / Ls[r];
        size_t oo = (size_t)(b*LL + q0 + r)*DD + h*HD + c0;
        #pragma unroll
        for (int q = 0; q < 4; q++) {
            float4 o = *(float4*)&Of[r*SLD + c0 + q*4];
            float4 g = *(const float4*)&g_G[oo + q*4];
            o.x *= inv * g.x; o.y *= inv * g.y;
            o.z *= inv * g.z; o.w *= inv * g.w;
            *(float4*)&g_O[oo + q*4] = o;
        }
    }
}

// ---------------------------------------------------------------------------
extern "C" void kernel_launch(void* const* d_in, const int* in_sizes, int n_in,
                              void* d_out, int out_size) {
    const float* query = (const float*)d_in[0];
    const float* key   = (const float*)d_in[1];
    const float* value = (const float*)d_in[2];
    const int*   mask  = (const int*)d_in[3];   // bool coerced to 32-bit by harness
    const float* rcos = (const float*)d_in[4];
    const float* rsin = (const float*)d_in[5];
    const float* Wq = (const float*)d_in[6];
    const float* bq = (const float*)d_in[7];
    const float* Wk = (const float*)d_in[8];
    const float* bk = (const float*)d_in[9];
    const float* Wv = (const float*)d_in[10];
    const float* bv = (const float*)d_in[11];
    const float* Wg = (const float*)d_in[12];
    const float* bg = (const float*)d_in[13];
    const float* Wo = (const float*)d_in[14];
    const float* bo = (const float*)d_in[15];
    float* out = (float*)d_out;

    void *pQ, *pK, *pV, *pG, *pO;
    cudaGetSymbolAddress(&pQ, g_Q);
    cudaGetSymbolAddress(&pK, g_K);
    cudaGetSymbolAddress(&pV, g_V);
    cudaGetSymbolAddress(&pG, g_G);
    cudaGetSymbolAddress(&pO, g_O);

    const int M = BN * LL;             // 4096
    dim3 blk(256);
    dim3 gproj(DD / 128, M / 128);     // 8 x 32

    const int gemm_smem = 65536;
    cudaFuncSetAttribute(gemm_bias_kernel<0>,
                         cudaFuncAttributeMaxDynamicSharedMemorySize, gemm_smem);
    cudaFuncSetAttribute(gemm_bias_kernel<1>,
                         cudaFuncAttributeMaxDynamicSharedMemorySize, gemm_smem);

    gemm_bias_kernel<0><<<gproj, blk, gemm_smem>>>(query, Wq, bq, (float*)pQ, M, DD, DD);
    gemm_bias_kernel<0><<<gproj, blk, gemm_smem>>>(key,   Wk, bk, (float*)pK, M, DD, DD);
    gemm_bias_kernel<0><<<gproj, blk, gemm_smem>>>(value, Wv, bv, (float*)pV, M, DD, DD);
    gemm_bias_kernel<1><<<gproj, blk, gemm_smem>>>(query, Wg, bg, (float*)pG, M, DD, DD);

    int nrope = BN * LL * HH * (HD / 2);
    rope_kernel<<<nrope / 256, 256>>>((float*)pQ, rcos, rsin);
    rope_kernel<<<nrope / 256, 256>>>((float*)pK, rcos, rsin);

    cudaFuncSetAttribute(flash_kernel,
                         cudaFuncAttributeMaxDynamicSharedMemorySize, FLASH_SMEM);
    flash_kernel<<<dim3(LL / 64, BH), blk, FLASH_SMEM>>>(mask);

    gemm_bias_kernel<0><<<gproj, blk, gemm_smem>>>((const float*)pO, Wo, bo, out, M, DD, DD);
}